// round 15
// baseline (speedup 1.0000x reference)
#include <cuda_runtime.h>
#include <cuda_fp16.h>
#include <cstdint>
#include <cstddef>

// out = x @ Wv^T + bv.  (Reference's softmax rows sum to 1 => its final
// einsum('btu,btj->btj', weights, v) == v + rounding; Q/K/softmax are dead.)
//
// Single-pass fp16 GEMM M=8192, K=1024, N=64 on portable mma.sync m16n8k16.
// R15 = R14 + ONE change: x cp.async carries .L2::256B prefetch. Theory: the
// measured 2.7 TB/s wall is per-SM outstanding-line (MSHR ~50) x 577-cyc DRAM
// latency; 256B prefetch halves requests/byte and converts half the fills to
// L2 hits -> ~2x stream rate at the same MSHR budget.

#define NEMB    1024
#define NH      64
#define MT      32
#define THREADS 256
#define GRID    256              // 8192 / 32
#define NCH     8                // K128 chunks
#define XPW     40               // fp32 words per row per K32 stage (LDS.64 conflict-free)
#define XSTG_W  (MT * XPW)       // 1280 words per stage
#define XSLOT_W (4 * XSTG_W)     // 5120 words per slot (K128)
#define XSLOT_B (XSLOT_W * 4)    // 20480 bytes
#define NSLOT   5
#define SMEM_BYTES (NSLOT * XSLOT_B)   // 102400

static_assert(SMEM_BYTES <= 113000, "2 CTAs/SM");

// W fragments (layout proven R9-R14): g_wf[(c*8+stp)*128 + (wn*2+p)*32 + lane]
__device__ uint4 g_wf[8192];

__global__ void wconv(const float* __restrict__ W)
{
    int id   = blockIdx.x * blockDim.x + threadIdx.x;   // 0..8191
    int lane = id & 31;
    int p    = (id >> 5) & 1;
    int wn   = (id >> 6) & 1;
    int s    = id >> 7;
    int k    = s * 16 + (lane & 3) * 2;
    int j0   = wn * 4 + p * 2;
    uint4 o;
#pragma unroll
    for (int jj = 0; jj < 2; jj++) {
        int n = (j0 + jj) * 8 + (lane >> 2);
        const float* ptr = W + (size_t)n * NEMB + k;
        __half2 h0 = __float22half2_rn(make_float2(ptr[0], ptr[1]));
        __half2 h1 = __float22half2_rn(make_float2(ptr[8], ptr[9]));
        if (jj == 0) { o.x = *(uint32_t*)&h0; o.y = *(uint32_t*)&h1; }
        else         { o.z = *(uint32_t*)&h0; o.w = *(uint32_t*)&h1; }
    }
    g_wf[id] = o;
}

__device__ __forceinline__ void mma16816(float* c,
                                         uint32_t a0, uint32_t a1, uint32_t a2, uint32_t a3,
                                         uint32_t b0, uint32_t b1)
{
    asm volatile(
        "mma.sync.aligned.m16n8k16.row.col.f32.f16.f16.f32 "
        "{%0,%1,%2,%3}, {%4,%5,%6,%7}, {%8,%9}, {%0,%1,%2,%3};"
        : "+f"(c[0]), "+f"(c[1]), "+f"(c[2]), "+f"(c[3])
        : "r"(a0), "r"(a1), "r"(a2), "r"(a3), "r"(b0), "r"(b1));
}

// x streaming copy WITH L2 256B prefetch (the R15 change)
__device__ __forceinline__ void cp16pf(uint32_t s, const void* g)
{
    asm volatile("cp.async.cg.shared.global.L2::256B [%0], [%1], 16;"
                 :: "r"(s), "l"(g));
}

__device__ __forceinline__ uint32_t packh2(float a, float b)
{
    __half2 h = __float22half2_rn(make_float2(a, b));
    return *(uint32_t*)&h;
}

__shared__ float bias_s[NH];
extern __shared__ char smem[];

__global__ void __launch_bounds__(THREADS)
vproj(const float* __restrict__ x, const float* __restrict__ bv,
      float* __restrict__ out)
{
    const int t   = threadIdx.x;
    const int wid = t >> 5;
    const int lid = t & 31;
    const int kh  = wid >> 2;         // K half: k16-steps kh*4 .. kh*4+3 per chunk
    const int wq  = wid & 3;
    const int wm  = wq & 1;           // M slice (16 rows)
    const int wn  = wq >> 1;          // N half (32 cols)
    const int rowbase = blockIdx.x * MT;

    float* xsm = (float*)smem;

    if (t < 16) ((float4*)bias_s)[t] = ((const float4*)bv)[t];

    const uint32_t xsm_s = (uint32_t)__cvta_generic_to_shared(xsm);

    // x producer mapping: row_t = t>>3 (0..31), c16 = t&7 (16B unit in 512B row-chunk)
    const int row_t = t >> 3;
    const int c16   = t & 7;
    const float* xrowp = x + (size_t)(rowbase + row_t) * NEMB + c16 * 4;
    const uint32_t xdst_base = xsm_s + (uint32_t)(row_t * XPW * 4 + c16 * 16);

#define XCOPY(g)                                                            \
    {                                                                       \
        if ((g) < NCH) {                                                    \
            const uint32_t xslot = (uint32_t)(((g) % NSLOT) * XSLOT_B);     \
            _Pragma("unroll")                                               \
            for (int s_ = 0; s_ < 4; s_++)                                  \
                cp16pf(xdst_base + xslot + (uint32_t)(s_ * XSTG_W * 4),     \
                       xrowp + (g) * 128 + s_ * 32);                        \
        }                                                                   \
        asm volatile("cp.async.commit_group;");                             \
    }

    const int wbase = wn * 64 + lid;

    // W register prefetch: this warp's 4 steps of chunk cc (L2-hot g_wf)
#define WLOAD(d0, d1, cc)                                                   \
    {                                                                       \
        if ((cc) < NCH) {                                                   \
            _Pragma("unroll")                                               \
            for (int s_ = 0; s_ < 4; s_++) {                                \
                d0[s_] = g_wf[((cc) * 8 + kh * 4 + s_) * 128 + wbase];      \
                d1[s_] = g_wf[((cc) * 8 + kh * 4 + s_) * 128 + wbase + 32]; \
            }                                                               \
        }                                                                   \
    }

    uint4 wa0[4], wa1[4], wb0[4], wb1[4];
    WLOAD(wa0, wa1, 0)

    XCOPY(0) XCOPY(1) XCOPY(2) XCOPY(3)
    asm volatile("cp.async.wait_group 3;");   // slot 0 ready
    __syncthreads();

    float acc[4][4];
#pragma unroll
    for (int j = 0; j < 4; j++)
#pragma unroll
        for (int e = 0; e < 4; e++) acc[j][e] = 0.0f;

    const int a_r   = wm * 16 + (lid >> 2);
    const int abase = a_r * XPW + (lid & 3) * 2;

#define LOAD_XFRAG(slot, xsl, stp)                                          \
    {                                                                       \
        const int stage_ = (stp) >> 1, st_ = (stp) & 1;                     \
        const float* ap = (xsl) + stage_ * XSTG_W + abase + st_ * 16;       \
        float2 f0 = *(const float2*)ap;                                     \
        float2 f1 = *(const float2*)(ap + 8 * XPW);                         \
        float2 f2 = *(const float2*)(ap + 8);                               \
        float2 f3 = *(const float2*)(ap + 8 * XPW + 8);                     \
        a0[slot] = packh2(f0.x, f0.y);                                      \
        a1[slot] = packh2(f1.x, f1.y);                                      \
        a2[slot] = packh2(f2.x, f2.y);                                      \
        a3[slot] = packh2(f3.x, f3.y);                                      \
    }
#define DO_MMAS(slot, W0, W1, s_)                                           \
    {                                                                       \
        mma16816(acc[0], a0[slot], a1[slot], a2[slot], a3[slot], W0[s_].x, W0[s_].y); \
        mma16816(acc[1], a0[slot], a1[slot], a2[slot], a3[slot], W0[s_].z, W0[s_].w); \
        mma16816(acc[2], a0[slot], a1[slot], a2[slot], a3[slot], W1[s_].x, W1[s_].y); \
        mma16816(acc[3], a0[slot], a1[slot], a2[slot], a3[slot], W1[s_].z, W1[s_].w); \
    }

#define CHUNK(c, C0, C1, N0, N1)                                            \
    {                                                                       \
        WLOAD(N0, N1, (c) + 1)                                              \
        const float* xsl = xsm + ((c) % NSLOT) * XSLOT_W;                   \
        uint32_t a0[2], a1[2], a2[2], a3[2];                                \
        LOAD_XFRAG(0, xsl, kh * 4 + 0)                                      \
        LOAD_XFRAG(1, xsl, kh * 4 + 1)                                      \
        DO_MMAS(0, C0, C1, 0)                                               \
        LOAD_XFRAG(0, xsl, kh * 4 + 2)                                      \
        DO_MMAS(1, C0, C1, 1)                                               \
        LOAD_XFRAG(1, xsl, kh * 4 + 3)                                      \
        DO_MMAS(0, C0, C1, 2)                                               \
        DO_MMAS(1, C0, C1, 3)                                               \
        __syncthreads();                                                    \
        XCOPY((c) + 4)                                                      \
        asm volatile("cp.async.wait_group 3;");                             \
    }

    CHUNK(0, wa0, wa1, wb0, wb1)
    CHUNK(1, wb0, wb1, wa0, wa1)
    CHUNK(2, wa0, wa1, wb0, wb1)
    CHUNK(3, wb0, wb1, wa0, wa1)
    CHUNK(4, wa0, wa1, wb0, wb1)
    CHUNK(5, wb0, wb1, wa0, wa1)
    CHUNK(6, wa0, wa1, wb0, wb1)
    CHUNK(7, wb0, wb1, wa0, wa1)

    // ---- K-split reduction + epilogue ----
    float* red = xsm;
    const int rbase = (wq * 32 + lid) * 20;
    __syncthreads();
    if (kh == 1) {
#pragma unroll
        for (int j = 0; j < 4; j++)
            *(float4*)(red + rbase + j * 4) = *(float4*)acc[j];
    }
    __syncthreads();
    if (kh == 0) {
        const int orow = rowbase + wm * 16 + (lid >> 2);
#pragma unroll
        for (int j = 0; j < 4; j++) {
            float4 o = *(float4*)(red + rbase + j * 4);
            const int col = wn * 32 + j * 8 + ((lid & 3) << 1);
            const float b0 = bias_s[col], b1 = bias_s[col + 1];
            float2 lo = make_float2(acc[j][0] + o.x + b0, acc[j][1] + o.y + b1);
            float2 hi = make_float2(acc[j][2] + o.z + b0, acc[j][3] + o.w + b1);
            *(float2*)(out + (size_t)orow * NH + col)       = lo;
            *(float2*)(out + (size_t)(orow + 8) * NH + col) = hi;
        }
    }
#undef XCOPY
#undef WLOAD
#undef LOAD_XFRAG
#undef DO_MMAS
#undef CHUNK
}

extern "C" void kernel_launch(void* const* d_in, const int* in_sizes, int n_in,
                              void* d_out, int out_size)
{
    const float* x  = (const float*)d_in[0];
    const float* Wv = (const float*)d_in[5];
    const float* bv = (const float*)d_in[6];

    cudaFuncSetAttribute(vproj, cudaFuncAttributeMaxDynamicSharedMemorySize, SMEM_BYTES);
    wconv<<<32, 256>>>(Wv);
    vproj<<<GRID, THREADS, SMEM_BYTES>>>(x, bv, (float*)d_out);
}